// round 2
// baseline (speedup 1.0000x reference)
#include <cuda_runtime.h>
#include <math.h>

#define NB 64
#define TT 512
#define DD 1024
#define HH 1024
#define FH 4096  // 4*H

// Scratch (device globals — no runtime allocation allowed)
__device__ float g_xz[(size_t)TT * NB * FH];  // (t, n, 4H) : 512 MB
__device__ float g_h[2][NB * HH];             // double-buffered hidden state
__device__ float g_c[NB * HH];                // cell state

// ---------------------------------------------------------------------------
// Init: h[0] = h0, c = 0
// ---------------------------------------------------------------------------
__global__ void init_kernel(const float* __restrict__ h0) {
    int i = blockIdx.x * blockDim.x + threadIdx.x;
    if (i < NB * HH) {
        g_h[0][i] = h0[i];
        g_c[i] = 0.0f;
    }
}

// ---------------------------------------------------------------------------
// GEMM1: xz[t][n][k] = sum_d x[n][t][d] * Wx[d][k] + b[k]
// x rows are already (n*512+t)*1024 contiguous, so A row m == x + m*1024.
// Output row is permuted to (t*64 + n).
// 128x128x16 tiles, 256 threads, 8x8 register tile per thread.
// ---------------------------------------------------------------------------
#define BM 128
#define BN 128
#define BK 16

__global__ __launch_bounds__(256) void gemm1_kernel(const float* __restrict__ X,
                                                    const float* __restrict__ Wx,
                                                    const float* __restrict__ b) {
    __shared__ __align__(16) float As[BK][BM];
    __shared__ __align__(16) float Bs[BK][BN];

    const int tid = threadIdx.x;
    const int m0 = blockIdx.y * BM;
    const int n0 = blockIdx.x * BN;
    const int tx = tid & 15;   // 0..15 (N dir)
    const int ty = tid >> 4;   // 0..15 (M dir)

    float acc[8][8];
#pragma unroll
    for (int i = 0; i < 8; i++)
#pragma unroll
        for (int j = 0; j < 8; j++) acc[i][j] = 0.0f;

    for (int k0 = 0; k0 < DD; k0 += BK) {
        // Load A tile (BM x BK), store transposed
#pragma unroll
        for (int i = 0; i < 2; i++) {
            int idx = tid + i * 256;           // 0..511
            int row = idx >> 2;                // 0..127
            int c4  = (idx & 3) << 2;          // 0,4,8,12
            float4 v = *(const float4*)(X + (size_t)(m0 + row) * DD + k0 + c4);
            As[c4 + 0][row] = v.x;
            As[c4 + 1][row] = v.y;
            As[c4 + 2][row] = v.z;
            As[c4 + 3][row] = v.w;
        }
        // Load B tile (BK x BN)
#pragma unroll
        for (int i = 0; i < 2; i++) {
            int idx = tid + i * 256;
            int row = idx >> 5;                // 0..15
            int c4  = (idx & 31) << 2;         // 0..124
            *(float4*)(&Bs[row][c4]) =
                *(const float4*)(Wx + (size_t)(k0 + row) * FH + n0 + c4);
        }
        __syncthreads();

#pragma unroll
        for (int kk = 0; kk < BK; kk++) {
            float4 a0 = *(const float4*)&As[kk][ty * 8 + 0];
            float4 a1 = *(const float4*)&As[kk][ty * 8 + 4];
            float4 b0 = *(const float4*)&Bs[kk][tx * 8 + 0];
            float4 b1 = *(const float4*)&Bs[kk][tx * 8 + 4];
            float ra[8] = {a0.x, a0.y, a0.z, a0.w, a1.x, a1.y, a1.z, a1.w};
            float rb[8] = {b0.x, b0.y, b0.z, b0.w, b1.x, b1.y, b1.z, b1.w};
#pragma unroll
            for (int i = 0; i < 8; i++)
#pragma unroll
                for (int j = 0; j < 8; j++) acc[i][j] += ra[i] * rb[j];
        }
        __syncthreads();
    }

    // Epilogue: permute row m = n*512+t -> xz row (t*64+n), add bias
#pragma unroll
    for (int i = 0; i < 8; i++) {
        int m = m0 + ty * 8 + i;
        int n = m >> 9;        // m / 512
        int t = m & 511;       // m % 512
        float* dst = g_xz + (size_t)(t * NB + n) * FH + n0 + tx * 8;
        const float* bp = b + n0 + tx * 8;
#pragma unroll
        for (int j = 0; j < 8; j++) dst[j] = acc[i][j] + bp[j];
    }
}

// ---------------------------------------------------------------------------
// Per-timestep fused kernel:
//   z = xz_t + h_prev @ Wh ; gates ; c,h update ; write out[:, t, :]
// Grid: 128 blocks, each owns 8 h-columns (J0..J0+7) across all 4 gates and
// all 64 batch rows. 256 threads: thread = (n-pair, j); 2x4 accumulators.
// h double-buffered across steps (all blocks read full h_prev).
// ---------------------------------------------------------------------------
#define HS_STRIDE 66   // even stride -> float2 loads stay 8B-aligned

__global__ __launch_bounds__(256) void lstm_step_kernel(const float* __restrict__ Wh,
                                                        float* __restrict__ out,
                                                        int t, int par) {
    __shared__ __align__(16) float  hs[32][HS_STRIDE];  // [kk][n]
    __shared__ __align__(16) float4 ws4[32][8];         // [kk][j] = (w_i,w_f,w_o,w_g)

    const float* __restrict__ hprev = g_h[par];
    float* __restrict__ hnext = g_h[par ^ 1];

    const int tid = threadIdx.x;
    const int J0 = blockIdx.x * 8;
    const int j  = tid & 7;
    const int np = tid >> 3;      // 0..31
    const int n0 = np << 1;

    float a00 = 0.f, a01 = 0.f, a02 = 0.f, a03 = 0.f;
    float a10 = 0.f, a11 = 0.f, a12 = 0.f, a13 = 0.f;

    for (int k0 = 0; k0 < HH; k0 += 32) {
        // Load h slice: 64 n x 32 k (coalesced rows of 32 floats)
#pragma unroll
        for (int i = 0; i < 8; i++) {
            int idx = tid + i * 256;     // 0..2047
            int n   = idx >> 5;
            int kk  = idx & 31;
            hs[kk][n] = hprev[n * HH + k0 + kk];
        }
        // Load Wh slice: 32 k x (8 j x 4 gates); j fastest -> 32B sectors
#pragma unroll
        for (int i = 0; i < 4; i++) {
            int idx = tid + i * 256;     // 0..1023
            int kk  = idx >> 5;
            int r   = idx & 31;
            int jj  = r & 7;
            int g   = r >> 3;
            ((float*)&ws4[kk][jj])[g] =
                Wh[(size_t)(k0 + kk) * FH + (g << 10) + J0 + jj];
        }
        __syncthreads();

#pragma unroll
        for (int kk = 0; kk < 32; kk++) {
            float2 hv = *(const float2*)&hs[kk][n0];
            float4 w  = ws4[kk][j];
            a00 += hv.x * w.x; a01 += hv.x * w.y; a02 += hv.x * w.z; a03 += hv.x * w.w;
            a10 += hv.y * w.x; a11 += hv.y * w.y; a12 += hv.y * w.z; a13 += hv.y * w.w;
        }
        __syncthreads();
    }

    // Fused gate epilogue for both batch rows
    const float* xzt = g_xz + (size_t)(t * NB) * FH;
#pragma unroll
    for (int c = 0; c < 2; c++) {
        int n = n0 + c;
        int col = J0 + j;
        const float* xr = xzt + (size_t)n * FH + col;
        float zi = (c ? a10 : a00) + xr[0];
        float zf = (c ? a11 : a01) + xr[1024];
        float zo = (c ? a12 : a02) + xr[2048];
        float zg = (c ? a13 : a03) + xr[3072];

        float iv = 1.0f / (1.0f + expf(-zi));
        float fv = 1.0f / (1.0f + expf(-zf));
        float ov = 1.0f / (1.0f + expf(-zo));
        float gv = tanhf(zg);

        int hidx = n * HH + col;
        float cn = fv * g_c[hidx] + iv * gv;
        g_c[hidx] = cn;
        float hn = ov * tanhf(cn);
        hnext[hidx] = hn;
        out[((size_t)n * TT + t) * HH + col] = hn;
    }
}

// ---------------------------------------------------------------------------
// Launcher (graph-capturable: kernel launches only)
// ---------------------------------------------------------------------------
extern "C" void kernel_launch(void* const* d_in, const int* in_sizes, int n_in,
                              void* d_out, int out_size) {
    const float* x  = (const float*)d_in[0];
    const float* h0 = (const float*)d_in[1];
    const float* Wx = (const float*)d_in[2];
    const float* Wh = (const float*)d_in[3];
    const float* b  = (const float*)d_in[4];
    float* out = (float*)d_out;

    init_kernel<<<(NB * HH + 255) / 256, 256>>>(h0);

    dim3 g1(FH / BN, (NB * TT) / BM);   // (32, 256)
    gemm1_kernel<<<g1, 256>>>(x, Wx, b);

    for (int t = 0; t < TT; t++) {
        lstm_step_kernel<<<HH / 8, 256>>>(Wh, out, t, t & 1);
    }
}

// round 3
// speedup vs baseline: 1.0576x; 1.0576x over previous
#include <cuda_runtime.h>
#include <math.h>

#define NB 64
#define TT 512
#define DD 1024
#define HH 1024
#define FH 4096  // 4*H

// Scratch (device globals — no runtime allocation allowed)
__device__ float g_xz[(size_t)TT * NB * FH];  // (t, n, 4H) : 512 MB
__device__ float g_h[2][NB * HH];             // double-buffered hidden state
__device__ float g_c[NB * HH];                // cell state

typedef unsigned long long ull;

// ---- packed f32x2 helpers (Blackwell sm_103a) ------------------------------
__device__ __forceinline__ ull ffma2(ull a, ull b, ull c) {
    ull d;
    asm("fma.rn.f32x2 %0, %1, %2, %3;" : "=l"(d) : "l"(a), "l"(b), "l"(c));
    return d;
}
__device__ __forceinline__ ull pack2(float lo, float hi) {
    ull d;
    asm("mov.b64 %0, {%1, %2};" : "=l"(d) : "f"(lo), "f"(hi));
    return d;
}
__device__ __forceinline__ void unpack2(ull v, float& lo, float& hi) {
    asm("mov.b64 {%0, %1}, %2;" : "=f"(lo), "=f"(hi) : "l"(v));
}

// ---------------------------------------------------------------------------
// Init: h[0] = h0, c = 0
// ---------------------------------------------------------------------------
__global__ void init_kernel(const float* __restrict__ h0) {
    int i = blockIdx.x * blockDim.x + threadIdx.x;
    if (i < NB * HH) {
        g_h[0][i] = h0[i];
        g_c[i] = 0.0f;
    }
}

// ---------------------------------------------------------------------------
// GEMM1: xz[t][n][k] = sum_d x[n][t][d] * Wx[d][k] + b[k]
// 128x128x16 tiles, 256 threads, 8x8 register tile per thread, FFMA2 inner.
// ---------------------------------------------------------------------------
#define BM 128
#define BN 128
#define BK 16

__global__ __launch_bounds__(256) void gemm1_kernel(const float* __restrict__ X,
                                                    const float* __restrict__ Wx,
                                                    const float* __restrict__ b) {
    __shared__ __align__(16) float As[BK][BM];
    __shared__ __align__(16) float Bs[BK][BN];

    const int tid = threadIdx.x;
    const int m0 = blockIdx.y * BM;
    const int n0 = blockIdx.x * BN;
    const int tx = tid & 15;   // 0..15 (N dir)
    const int ty = tid >> 4;   // 0..15 (M dir)

    ull acc2[8][4];
#pragma unroll
    for (int i = 0; i < 8; i++)
#pragma unroll
        for (int j = 0; j < 4; j++) acc2[i][j] = 0ull;

    for (int k0 = 0; k0 < DD; k0 += BK) {
        // Load A tile (BM x BK), store transposed
#pragma unroll
        for (int i = 0; i < 2; i++) {
            int idx = tid + i * 256;           // 0..511
            int row = idx >> 2;                // 0..127
            int c4  = (idx & 3) << 2;          // 0,4,8,12
            float4 v = *(const float4*)(X + (size_t)(m0 + row) * DD + k0 + c4);
            As[c4 + 0][row] = v.x;
            As[c4 + 1][row] = v.y;
            As[c4 + 2][row] = v.z;
            As[c4 + 3][row] = v.w;
        }
        // Load B tile (BK x BN)
#pragma unroll
        for (int i = 0; i < 2; i++) {
            int idx = tid + i * 256;
            int row = idx >> 5;                // 0..15
            int c4  = (idx & 31) << 2;         // 0..124
            *(float4*)(&Bs[row][c4]) =
                *(const float4*)(Wx + (size_t)(k0 + row) * FH + n0 + c4);
        }
        __syncthreads();

#pragma unroll
        for (int kk = 0; kk < BK; kk++) {
            float4 a0 = *(const float4*)&As[kk][ty * 8 + 0];
            float4 a1 = *(const float4*)&As[kk][ty * 8 + 4];
            ulonglong2 bb0 = *(const ulonglong2*)&Bs[kk][tx * 8 + 0];
            ulonglong2 bb1 = *(const ulonglong2*)&Bs[kk][tx * 8 + 4];
            float ra[8] = {a0.x, a0.y, a0.z, a0.w, a1.x, a1.y, a1.z, a1.w};
            ull rbp[4] = {bb0.x, bb0.y, bb1.x, bb1.y};
#pragma unroll
            for (int i = 0; i < 8; i++) {
                ull ai = pack2(ra[i], ra[i]);
#pragma unroll
                for (int j = 0; j < 4; j++)
                    acc2[i][j] = ffma2(ai, rbp[j], acc2[i][j]);
            }
        }
        __syncthreads();
    }

    // Epilogue: permute row m = n*512+t -> xz row (t*64+n), add bias
#pragma unroll
    for (int i = 0; i < 8; i++) {
        int m = m0 + ty * 8 + i;
        int n = m >> 9;        // m / 512
        int t = m & 511;       // m % 512
        float* dst = g_xz + (size_t)(t * NB + n) * FH + n0 + tx * 8;
        const float* bp = b + n0 + tx * 8;
#pragma unroll
        for (int j = 0; j < 4; j++) {
            float lo, hi;
            unpack2(acc2[i][j], lo, hi);
            dst[j * 2 + 0] = lo + bp[j * 2 + 0];
            dst[j * 2 + 1] = hi + bp[j * 2 + 1];
        }
    }
}

// ---------------------------------------------------------------------------
// Per-timestep fused kernel (FFMA2 inner loop):
//   z = xz_t + h_prev @ Wh ; gates ; c,h update ; write out[:, t, :]
// 128 blocks (8 h-cols x 4 gates = 32 gate-cols each), 256 threads.
// Thread tile 4n x 2c; acc in packed f32x2 (pairs over n).
// Gate fusion via smem z-exchange after the GEMM phase.
// ---------------------------------------------------------------------------
#define KB 64           // k-slab
#define HS_STR 68       // hs row stride (16B-aligned rows: 68*4=272)
#define WS_STR 36       // ws row stride (16B-aligned rows: 36*4=144)

__global__ __launch_bounds__(256) void lstm_step_kernel(const float* __restrict__ Wh,
                                                        float* __restrict__ out,
                                                        int t, int par) {
    __shared__ __align__(16) float hs[KB][HS_STR];   // [kk][n]
    __shared__ __align__(16) float ws[KB][WS_STR];   // [kk][c], c = g*8+j
    __shared__ __align__(16) float zbuf[NB][33];     // [n][c]

    const float* __restrict__ hprev = g_h[par];
    float* __restrict__ hnext = g_h[par ^ 1];

    const int tid = threadIdx.x;
    const int J0 = blockIdx.x * 8;
    const int cg = tid & 15;       // c-group: cols c0=cg*2, c0+1
    const int ng = tid >> 4;       // n-group: rows ng*4 .. +3
    const int c0 = cg * 2;
    const int nb = ng * 4;

    ull acc[2][2];   // [cc][npair]; npair p covers rows nb+2p, nb+2p+1
    acc[0][0] = acc[0][1] = acc[1][0] = acc[1][1] = 0ull;

    for (int k0 = 0; k0 < HH; k0 += KB) {
        // Stage h slice: 64 n x 64 k  (float4 along k)
#pragma unroll
        for (int i = 0; i < 4; i++) {
            int f = tid + i * 256;          // 0..1023 float4s
            int n = f >> 4;
            int k4 = (f & 15) << 2;
            float4 v = *(const float4*)&hprev[n * HH + k0 + k4];
            hs[k4 + 0][n] = v.x;
            hs[k4 + 1][n] = v.y;
            hs[k4 + 2][n] = v.z;
            hs[k4 + 3][n] = v.w;
        }
        // Stage Wh slice: 64 k x 32 c (c = g*8+j), float4 chunks
#pragma unroll
        for (int i = 0; i < 2; i++) {
            int f = tid + i * 256;          // 0..511 float4s
            int kk = f >> 3;
            int r = f & 7;
            int g = r >> 1;
            int jq = (r & 1) << 2;
            float4 v = *(const float4*)&Wh[(size_t)(k0 + kk) * FH + (g << 10) + J0 + jq];
            *(float4*)&ws[kk][g * 8 + jq] = v;
        }
        __syncthreads();

#pragma unroll
        for (int kk = 0; kk < KB; kk++) {
            ulonglong2 hp = *(const ulonglong2*)&hs[kk][nb];   // (h0,h1),(h2,h3)
            float2 w2 = *(const float2*)&ws[kk][c0];
            ull w0 = pack2(w2.x, w2.x);
            ull w1 = pack2(w2.y, w2.y);
            acc[0][0] = ffma2(hp.x, w0, acc[0][0]);
            acc[0][1] = ffma2(hp.y, w0, acc[0][1]);
            acc[1][0] = ffma2(hp.x, w1, acc[1][0]);
            acc[1][1] = ffma2(hp.y, w1, acc[1][1]);
        }
        __syncthreads();
    }

    // Exchange z partials through smem so each thread can fuse all 4 gates
#pragma unroll
    for (int cc = 0; cc < 2; cc++)
#pragma unroll
        for (int p = 0; p < 2; p++) {
            float lo, hi;
            unpack2(acc[cc][p], lo, hi);
            zbuf[nb + 2 * p + 0][c0 + cc] = lo;
            zbuf[nb + 2 * p + 1][c0 + cc] = hi;
        }
    __syncthreads();

    // Gate epilogue: 512 (n,j) outputs, 2 per thread
    const float* xzt = g_xz + (size_t)(t * NB) * FH;
#pragma unroll
    for (int s = 0; s < 2; s++) {
        int idx = tid + s * 256;     // 0..511
        int n = idx >> 3;
        int j = idx & 7;
        int col = J0 + j;
        const float* xr = xzt + (size_t)n * FH + col;
        float zi = zbuf[n][j +  0] + xr[0];
        float zf = zbuf[n][j +  8] + xr[1024];
        float zo = zbuf[n][j + 16] + xr[2048];
        float zg = zbuf[n][j + 24] + xr[3072];

        float iv = 1.0f / (1.0f + expf(-zi));
        float fv = 1.0f / (1.0f + expf(-zf));
        float ov = 1.0f / (1.0f + expf(-zo));
        float gv = tanhf(zg);

        int hidx = n * HH + col;
        float cn = fv * g_c[hidx] + iv * gv;
        g_c[hidx] = cn;
        float hn = ov * tanhf(cn);
        hnext[hidx] = hn;
        out[((size_t)n * TT + t) * HH + col] = hn;
    }
}

// ---------------------------------------------------------------------------
// Launcher (graph-capturable: kernel launches only)
// ---------------------------------------------------------------------------
extern "C" void kernel_launch(void* const* d_in, const int* in_sizes, int n_in,
                              void* d_out, int out_size) {
    const float* x  = (const float*)d_in[0];
    const float* h0 = (const float*)d_in[1];
    const float* Wx = (const float*)d_in[2];
    const float* Wh = (const float*)d_in[3];
    const float* b  = (const float*)d_in[4];
    float* out = (float*)d_out;

    init_kernel<<<(NB * HH + 255) / 256, 256>>>(h0);

    dim3 g1(FH / BN, (NB * TT) / BM);   // (32, 256)
    gemm1_kernel<<<g1, 256>>>(x, Wx, b);

    for (int t = 0; t < TT; t++) {
        lstm_step_kernel<<<HH / 8, 256>>>(Wh, out, t, t & 1);
    }
}

// round 4
// speedup vs baseline: 1.0990x; 1.0391x over previous
#include <cuda_runtime.h>
#include <cuda_bf16.h>
#include <math.h>

#define NB 64
#define TT 512
#define DD 1024
#define HH 1024
#define FH 4096   // 4*H
#define KSTACK 3072

typedef unsigned long long ull;

// Scratch (device globals — no runtime allocation allowed)
__device__ float g_xz[(size_t)TT * NB * FH];          // (t, n, 4H) : 512 MB
__device__ __nv_bfloat16 g_wstack[(size_t)KSTACK * FH]; // [k][blk*32+cl] : 25 MB
__device__ __nv_bfloat16 g_hh[2][NB * HH];            // h hi, double-buffered
__device__ __nv_bfloat16 g_hl[2][NB * HH];            // h lo
__device__ float g_c[NB * HH];                        // cell state

// ---- packed f32x2 helpers (for fp32 GEMM1) ---------------------------------
__device__ __forceinline__ ull ffma2(ull a, ull b, ull c) {
    ull d;
    asm("fma.rn.f32x2 %0, %1, %2, %3;" : "=l"(d) : "l"(a), "l"(b), "l"(c));
    return d;
}
__device__ __forceinline__ ull pack2(float lo, float hi) {
    ull d;
    asm("mov.b64 %0, {%1, %2};" : "=l"(d) : "f"(lo), "f"(hi));
    return d;
}
__device__ __forceinline__ void unpack2(ull v, float& lo, float& hi) {
    asm("mov.b64 {%0, %1}, %2;" : "=f"(lo), "=f"(hi) : "l"(v));
}
__device__ __forceinline__ unsigned s2u(const void* p) {
    return (unsigned)__cvta_generic_to_shared(p);
}

// ---------------------------------------------------------------------------
// Init: split h0 -> (hh, hl); c = 0
// ---------------------------------------------------------------------------
__global__ void init_kernel(const float* __restrict__ h0) {
    int i = blockIdx.x * blockDim.x + threadIdx.x;
    if (i < NB * HH) {
        float v = h0[i];
        __nv_bfloat16 hi = __float2bfloat16(v);
        g_hh[0][i] = hi;
        g_hl[0][i] = __float2bfloat16(v - __bfloat162float(hi));
        g_c[i] = 0.0f;
    }
}

// ---------------------------------------------------------------------------
// Precompute W_stack (split-bf16, K-stacked, block-permuted columns):
//   region 0: W_hi ; region 1: W_lo ; region 2: W_hi
// Column layout: [k][blk][cl] with cl = g*8 + j, blk = (col%1024)/8, g = col/1024
// ---------------------------------------------------------------------------
__global__ void split_wh_kernel(const float* __restrict__ Wh) {
    int i = blockIdx.x * blockDim.x + threadIdx.x;
    if (i >= DD * FH) return;
    int k = i >> 12;
    int co = i & 4095;
    float w = Wh[i];
    __nv_bfloat16 hi = __float2bfloat16(w);
    __nv_bfloat16 lo = __float2bfloat16(w - __bfloat162float(hi));
    int g = co >> 10;
    int within = co & 1023;
    int blk = within >> 3;
    int j = within & 7;
    size_t col = (size_t)blk * 32 + g * 8 + j;
    g_wstack[(size_t)k * FH + col] = hi;
    g_wstack[(size_t)(k + 1024) * FH + col] = lo;
    g_wstack[(size_t)(k + 2048) * FH + col] = hi;
}

// ---------------------------------------------------------------------------
// GEMM1 (fp32 FFMA2): xz[t][n][k] = sum_d x[n][t][d] * Wx[d][k] + b[k]
// ---------------------------------------------------------------------------
#define BM 128
#define BN 128
#define BK 16

__global__ __launch_bounds__(256) void gemm1_kernel(const float* __restrict__ X,
                                                    const float* __restrict__ Wx,
                                                    const float* __restrict__ b) {
    __shared__ __align__(16) float As[BK][BM];
    __shared__ __align__(16) float Bs[BK][BN];

    const int tid = threadIdx.x;
    const int m0 = blockIdx.y * BM;
    const int n0 = blockIdx.x * BN;
    const int tx = tid & 15;
    const int ty = tid >> 4;

    ull acc2[8][4];
#pragma unroll
    for (int i = 0; i < 8; i++)
#pragma unroll
        for (int j = 0; j < 4; j++) acc2[i][j] = 0ull;

    for (int k0 = 0; k0 < DD; k0 += BK) {
#pragma unroll
        for (int i = 0; i < 2; i++) {
            int idx = tid + i * 256;
            int row = idx >> 2;
            int c4  = (idx & 3) << 2;
            float4 v = *(const float4*)(X + (size_t)(m0 + row) * DD + k0 + c4);
            As[c4 + 0][row] = v.x;
            As[c4 + 1][row] = v.y;
            As[c4 + 2][row] = v.z;
            As[c4 + 3][row] = v.w;
        }
#pragma unroll
        for (int i = 0; i < 2; i++) {
            int idx = tid + i * 256;
            int row = idx >> 5;
            int c4  = (idx & 31) << 2;
            *(float4*)(&Bs[row][c4]) =
                *(const float4*)(Wx + (size_t)(k0 + row) * FH + n0 + c4);
        }
        __syncthreads();

#pragma unroll
        for (int kk = 0; kk < BK; kk++) {
            float4 a0 = *(const float4*)&As[kk][ty * 8 + 0];
            float4 a1 = *(const float4*)&As[kk][ty * 8 + 4];
            ulonglong2 bb0 = *(const ulonglong2*)&Bs[kk][tx * 8 + 0];
            ulonglong2 bb1 = *(const ulonglong2*)&Bs[kk][tx * 8 + 4];
            float ra[8] = {a0.x, a0.y, a0.z, a0.w, a1.x, a1.y, a1.z, a1.w};
            ull rbp[4] = {bb0.x, bb0.y, bb1.x, bb1.y};
#pragma unroll
            for (int i = 0; i < 8; i++) {
                ull ai = pack2(ra[i], ra[i]);
#pragma unroll
                for (int j = 0; j < 4; j++)
                    acc2[i][j] = ffma2(ai, rbp[j], acc2[i][j]);
            }
        }
        __syncthreads();
    }

#pragma unroll
    for (int i = 0; i < 8; i++) {
        int m = m0 + ty * 8 + i;
        int n = m >> 9;
        int t = m & 511;
        float* dst = g_xz + (size_t)(t * NB + n) * FH + n0 + tx * 8;
        const float* bp = b + n0 + tx * 8;
#pragma unroll
        for (int j = 0; j < 4; j++) {
            float lo, hi;
            unpack2(acc2[i][j], lo, hi);
            dst[j * 2 + 0] = lo + bp[j * 2 + 0];
            dst[j * 2 + 1] = hi + bp[j * 2 + 1];
        }
    }
}

// ---------------------------------------------------------------------------
// Per-timestep fused kernel (split-bf16 tensor-core GEMM + gates):
//   z[n][c] = sum_{k<3072} hstack[n][k] * wstack[k][c]   (c = g*8+j, 32 per blk)
// 128 blocks x 256 threads (8 warps in 2(m) x 4(c) grid).
// mma.sync.m16n8k16.bf16: each warp M=32 (2 m-tiles) x N=8.
// ---------------------------------------------------------------------------
__global__ __launch_bounds__(256) void lstm_step_kernel(float* __restrict__ out,
                                                        int t, int par) {
    __shared__ __align__(16) __nv_bfloat16 hs[64][72];  // 144 B rows (odd*16)
    __shared__ __align__(16) __nv_bfloat16 ws[64][40];  // 80 B rows (odd*16)
    __shared__ __align__(16) float zbuf[NB][33];

    const int tid = threadIdx.x;
    const int lane = tid & 31;
    const int wid = tid >> 5;
    const int warp_m = wid >> 2;   // 0..1
    const int warp_c = wid & 3;    // 0..3

    const __nv_bfloat16* __restrict__ hh = g_hh[par];
    const __nv_bfloat16* __restrict__ hl = g_hl[par];
    const __nv_bfloat16* __restrict__ wst = g_wstack + (size_t)blockIdx.x * 32;

    float d[2][4];
#pragma unroll
    for (int mt = 0; mt < 2; mt++)
#pragma unroll
        for (int r = 0; r < 4; r++) d[mt][r] = 0.0f;

    // Precomputed ldmatrix lane addressing
    const int lr = lane & 7;
    const int lg = lane >> 3;
    const int a_row_off = ((lg & 1) << 3) + lr;     // row within 16
    const int a_k_off = (lg >> 1) << 3;             // 0 or 8
    const int b_krow = lane & 15;

    for (int slab = 0; slab < KSTACK / 64; slab++) {
        const int k0 = slab * 64;
        const __nv_bfloat16* hsrc = (k0 < 2048) ? hh : hl;
        const int hk = k0 & 1023;

        // Stage h slab: 64n x 64k bf16 (2 x uint4 per thread)
#pragma unroll
        for (int i = 0; i < 2; i++) {
            int idx = tid + i * 256;
            int n = idx >> 3;
            int ch = idx & 7;
            *(uint4*)&hs[n][ch * 8] =
                *(const uint4*)&hsrc[n * HH + hk + ch * 8];
        }
        // Stage W slab: 64k x 32c bf16 (1 x uint4 per thread)
        {
            int kk = tid >> 2;
            int ch = tid & 3;
            *(uint4*)&ws[kk][ch * 8] =
                *(const uint4*)&wst[(size_t)(k0 + kk) * FH + ch * 8];
        }
        __syncthreads();

#pragma unroll
        for (int ks = 0; ks < 4; ks++) {
            const int kk0 = ks * 16;
            // B fragment: ldmatrix.x2.trans from ws[k][c]
            unsigned b0, b1;
            {
                unsigned addr = s2u(&ws[kk0 + b_krow][warp_c * 8]);
                asm volatile(
                    "ldmatrix.sync.aligned.m8n8.x2.trans.shared.b16 {%0,%1}, [%2];"
                    : "=r"(b0), "=r"(b1) : "r"(addr));
            }
#pragma unroll
            for (int mt = 0; mt < 2; mt++) {
                unsigned a0, a1, a2, a3;
                int row = warp_m * 32 + mt * 16 + a_row_off;
                unsigned addr = s2u(&hs[row][kk0 + a_k_off]);
                asm volatile(
                    "ldmatrix.sync.aligned.m8n8.x4.shared.b16 {%0,%1,%2,%3}, [%4];"
                    : "=r"(a0), "=r"(a1), "=r"(a2), "=r"(a3) : "r"(addr));
                asm volatile(
                    "mma.sync.aligned.m16n8k16.row.col.f32.bf16.bf16.f32 "
                    "{%0,%1,%2,%3}, {%4,%5,%6,%7}, {%8,%9}, {%0,%1,%2,%3};"
                    : "+f"(d[mt][0]), "+f"(d[mt][1]), "+f"(d[mt][2]), "+f"(d[mt][3])
                    : "r"(a0), "r"(a1), "r"(a2), "r"(a3), "r"(b0), "r"(b1));
            }
        }
        __syncthreads();
    }

    // Scatter accumulators to zbuf[n][c]
    {
        const int r4 = lane >> 2;
        const int c2 = (lane & 3) * 2;
        const int c = warp_c * 8 + c2;
#pragma unroll
        for (int mt = 0; mt < 2; mt++) {
            int n = warp_m * 32 + mt * 16 + r4;
            zbuf[n][c] = d[mt][0];
            zbuf[n][c + 1] = d[mt][1];
            zbuf[n + 8][c] = d[mt][2];
            zbuf[n + 8][c + 1] = d[mt][3];
        }
    }
    __syncthreads();

    // Gate epilogue: 512 (n,j) outputs, 2 per thread
    const int J0 = blockIdx.x * 8;
    const float* xzt = g_xz + (size_t)(t * NB) * FH;
    __nv_bfloat16* __restrict__ hhn = g_hh[par ^ 1];
    __nv_bfloat16* __restrict__ hln = g_hl[par ^ 1];
#pragma unroll
    for (int s = 0; s < 2; s++) {
        int idx = tid + s * 256;
        int n = idx >> 3;
        int j = idx & 7;
        int col = J0 + j;
        const float* xr = xzt + (size_t)n * FH + col;
        float zi = zbuf[n][j +  0] + xr[0];
        float zf = zbuf[n][j +  8] + xr[1024];
        float zo = zbuf[n][j + 16] + xr[2048];
        float zg = zbuf[n][j + 24] + xr[3072];

        float iv = 1.0f / (1.0f + expf(-zi));
        float fv = 1.0f / (1.0f + expf(-zf));
        float ov = 1.0f / (1.0f + expf(-zo));
        float gv = tanhf(zg);

        int hidx = n * HH + col;
        float cn = fv * g_c[hidx] + iv * gv;
        g_c[hidx] = cn;
        float hn = ov * tanhf(cn);

        __nv_bfloat16 hi = __float2bfloat16(hn);
        hhn[hidx] = hi;
        hln[hidx] = __float2bfloat16(hn - __bfloat162float(hi));
        out[((size_t)n * TT + t) * HH + col] = hn;
    }
}

// ---------------------------------------------------------------------------
// Launcher (graph-capturable: kernel launches only)
// ---------------------------------------------------------------------------
extern "C" void kernel_launch(void* const* d_in, const int* in_sizes, int n_in,
                              void* d_out, int out_size) {
    const float* x  = (const float*)d_in[0];
    const float* h0 = (const float*)d_in[1];
    const float* Wx = (const float*)d_in[2];
    const float* Wh = (const float*)d_in[3];
    const float* b  = (const float*)d_in[4];
    float* out = (float*)d_out;

    init_kernel<<<(NB * HH + 255) / 256, 256>>>(h0);
    split_wh_kernel<<<(DD * FH + 255) / 256, 256>>>(Wh);

    dim3 g1(FH / BN, (NB * TT) / BM);   // (32, 256)
    gemm1_kernel<<<g1, 256>>>(x, Wx, b);

    for (int t = 0; t < TT; t++) {
        lstm_step_kernel<<<HH / 8, 256>>>(out, t, t & 1);
    }
}

// round 5
// speedup vs baseline: 1.7665x; 1.6074x over previous
#include <cuda_runtime.h>
#include <cuda_bf16.h>
#include <math.h>

#define NB 64
#define TT 512
#define DD 1024
#define HH 1024
#define FH 4096   // 4*H

typedef unsigned long long ull;

// Scratch (device globals — no runtime allocation allowed)
__device__ float g_xz[(size_t)TT * NB * FH];            // (t, n, 4H) : 512 MB
__device__ __nv_bfloat16 g_wsplit[(size_t)2048 * FH];   // rows 0-1023: Wh_hi, 1024-2047: Wh_lo (cols permuted)
__device__ __nv_bfloat16 g_hh[2][NB * HH];              // h hi, double-buffered
__device__ __nv_bfloat16 g_hl[2][NB * HH];              // h lo
__device__ unsigned g_bar_count;
__device__ unsigned g_bar_phase;

// ---- helpers ----------------------------------------------------------------
__device__ __forceinline__ ull ffma2(ull a, ull b, ull c) {
    ull d;
    asm("fma.rn.f32x2 %0, %1, %2, %3;" : "=l"(d) : "l"(a), "l"(b), "l"(c));
    return d;
}
__device__ __forceinline__ ull pack2(float lo, float hi) {
    ull d;
    asm("mov.b64 %0, {%1, %2};" : "=l"(d) : "f"(lo), "f"(hi));
    return d;
}
__device__ __forceinline__ void unpack2(ull v, float& lo, float& hi) {
    asm("mov.b64 {%0, %1}, %2;" : "=f"(lo), "=f"(hi) : "l"(v));
}
__device__ __forceinline__ unsigned s2u(const void* p) {
    return (unsigned)__cvta_generic_to_shared(p);
}
__device__ __forceinline__ void cp16(void* s, const void* g) {
    asm volatile("cp.async.cg.shared.global [%0], [%1], 16;" :: "r"(s2u(s)), "l"(g));
}
__device__ __forceinline__ unsigned ld_acquire(unsigned* p) {
    unsigned v;
    asm volatile("ld.acquire.gpu.u32 %0, [%1];" : "=r"(v) : "l"(p) : "memory");
    return v;
}
__device__ __forceinline__ void st_release(unsigned* p, unsigned v) {
    asm volatile("st.release.gpu.u32 [%0], %1;" :: "l"(p), "r"(v) : "memory");
}

// ---------------------------------------------------------------------------
// Init: split h0 -> (hh, hl); reset grid barrier
// ---------------------------------------------------------------------------
__global__ void init_kernel(const float* __restrict__ h0) {
    int i = blockIdx.x * blockDim.x + threadIdx.x;
    if (i == 0) { g_bar_count = 0; g_bar_phase = 0; }
    if (i < NB * HH) {
        float v = h0[i];
        __nv_bfloat16 hi = __float2bfloat16(v);
        g_hh[0][i] = hi;
        g_hl[0][i] = __float2bfloat16(v - __bfloat162float(hi));
    }
}

// ---------------------------------------------------------------------------
// Precompute split-bf16 Wh, columns permuted so each block's 32 gate-cols
// (cl = g*8+j for its 8 h-cols) are contiguous:
//   col_new = blk*32 + g*8 + j   where original col = g*1024 + blk*8 + j
// ---------------------------------------------------------------------------
__global__ void split_wh_kernel(const float* __restrict__ Wh) {
    int i = blockIdx.x * blockDim.x + threadIdx.x;
    if (i >= DD * FH) return;
    int k = i >> 12;
    int co = i & 4095;
    float w = Wh[i];
    __nv_bfloat16 hi = __float2bfloat16(w);
    __nv_bfloat16 lo = __float2bfloat16(w - __bfloat162float(hi));
    int g = co >> 10;
    int within = co & 1023;
    int blk = within >> 3;
    int j = within & 7;
    size_t col = (size_t)blk * 32 + g * 8 + j;
    g_wsplit[(size_t)k * FH + col] = hi;
    g_wsplit[(size_t)(k + 1024) * FH + col] = lo;
}

// ---------------------------------------------------------------------------
// GEMM1 (fp32 FFMA2): xz[t][n][k] = sum_d x[n][t][d] * Wx[d][k] + b[k]
// ---------------------------------------------------------------------------
#define BM 128
#define BN 128
#define BK 16

__global__ __launch_bounds__(256) void gemm1_kernel(const float* __restrict__ X,
                                                    const float* __restrict__ Wx,
                                                    const float* __restrict__ b) {
    __shared__ __align__(16) float As[BK][BM];
    __shared__ __align__(16) float Bs[BK][BN];

    const int tid = threadIdx.x;
    const int m0 = blockIdx.y * BM;
    const int n0 = blockIdx.x * BN;
    const int tx = tid & 15;
    const int ty = tid >> 4;

    ull acc2[8][4];
#pragma unroll
    for (int i = 0; i < 8; i++)
#pragma unroll
        for (int j = 0; j < 4; j++) acc2[i][j] = 0ull;

    for (int k0 = 0; k0 < DD; k0 += BK) {
#pragma unroll
        for (int i = 0; i < 2; i++) {
            int idx = tid + i * 256;
            int row = idx >> 2;
            int c4  = (idx & 3) << 2;
            float4 v = *(const float4*)(X + (size_t)(m0 + row) * DD + k0 + c4);
            As[c4 + 0][row] = v.x;
            As[c4 + 1][row] = v.y;
            As[c4 + 2][row] = v.z;
            As[c4 + 3][row] = v.w;
        }
#pragma unroll
        for (int i = 0; i < 2; i++) {
            int idx = tid + i * 256;
            int row = idx >> 5;
            int c4  = (idx & 31) << 2;
            *(float4*)(&Bs[row][c4]) =
                *(const float4*)(Wx + (size_t)(k0 + row) * FH + n0 + c4);
        }
        __syncthreads();

#pragma unroll
        for (int kk = 0; kk < BK; kk++) {
            float4 a0 = *(const float4*)&As[kk][ty * 8 + 0];
            float4 a1 = *(const float4*)&As[kk][ty * 8 + 4];
            ulonglong2 bb0 = *(const ulonglong2*)&Bs[kk][tx * 8 + 0];
            ulonglong2 bb1 = *(const ulonglong2*)&Bs[kk][tx * 8 + 4];
            float ra[8] = {a0.x, a0.y, a0.z, a0.w, a1.x, a1.y, a1.z, a1.w};
            ull rbp[4] = {bb0.x, bb0.y, bb1.x, bb1.y};
#pragma unroll
            for (int i = 0; i < 8; i++) {
                ull ai = pack2(ra[i], ra[i]);
#pragma unroll
                for (int j = 0; j < 4; j++)
                    acc2[i][j] = ffma2(ai, rbp[j], acc2[i][j]);
            }
        }
        __syncthreads();
    }

#pragma unroll
    for (int i = 0; i < 8; i++) {
        int m = m0 + ty * 8 + i;
        int n = m >> 9;
        int t = m & 511;
        float* dst = g_xz + (size_t)(t * NB + n) * FH + n0 + tx * 8;
        const float* bp = b + n0 + tx * 8;
#pragma unroll
        for (int j = 0; j < 4; j++) {
            float lo, hi;
            unpack2(acc2[i][j], lo, hi);
            dst[j * 2 + 0] = lo + bp[j * 2 + 0];
            dst[j * 2 + 1] = hi + bp[j * 2 + 1];
        }
    }
}

// ---------------------------------------------------------------------------
// Persistent recurrence kernel.
// 128 blocks (1/SM), 256 threads (8 warps: 2m x 4c). Block b owns gate-cols
// cl = g*8+j for h-cols J0..J0+7 (J0 = b*8). W slice (hi+lo) lives in SMEM
// for all 512 steps. h slabs streamed via double-buffered cp.async.
// Split-bf16: z = h_hi*W_hi + h_hi*W_lo + h_lo*W_hi.
// ---------------------------------------------------------------------------
#define WS_STR 40   // bf16; 80-byte rows (odd multiple of 16B -> conflict-free ldsm)
#define HS_STR 72   // bf16; 144-byte rows
#define SMEM_WS_BYTES (2048 * WS_STR * 2)                     // 163840
#define SMEM_HS_OFF   SMEM_WS_BYTES
#define SMEM_HS_BYTES (2 * 64 * HS_STR * 2)                   // 18432
#define SMEM_ZB_OFF   (SMEM_HS_OFF + SMEM_HS_BYTES)
#define SMEM_TOTAL    (SMEM_ZB_OFF + 64 * 33 * 4)             // 190720

__global__ __launch_bounds__(256, 1) void lstm_persistent(float* __restrict__ out) {
    extern __shared__ __align__(16) char sm_raw[];
    __nv_bfloat16* ws = (__nv_bfloat16*)sm_raw;                    // [2048][WS_STR]
    __nv_bfloat16* hsm = (__nv_bfloat16*)(sm_raw + SMEM_HS_OFF);   // [2][64][HS_STR]
    float* zbuf = (float*)(sm_raw + SMEM_ZB_OFF);                  // [64][33]

    const int tid = threadIdx.x;
    const int lane = tid & 31;
    const int wid = tid >> 5;
    const int warp_m = wid >> 2;   // 0..1
    const int warp_c = wid & 3;    // 0..3
    const int blk = blockIdx.x;

    // --- Load this block's W slice into SMEM (once) ---
    {
        const __nv_bfloat16* wsrc = g_wsplit + (size_t)blk * 32;
#pragma unroll
        for (int i = 0; i < 32; i++) {
            int c = tid + i * 256;          // 0..8191 16B-chunks
            int row = c >> 2;
            int q = c & 3;
            *(uint4*)&ws[row * WS_STR + q * 8] =
                *(const uint4*)&wsrc[(size_t)row * FH + q * 8];
        }
    }
    __syncthreads();

    // ldmatrix lane addressing
    const int lr = lane & 7;
    const int lg = lane >> 3;
    const int a_row_off = ((lg & 1) << 3) + lr;
    const int a_k_off = (lg >> 1) << 3;
    const int b_krow = lane & 15;

    // epilogue mapping (fixed per thread across all steps)
    const int e_n0 = tid >> 3;            // output 0: n
    const int e_j = tid & 7;              //           j
    const int e_n1 = (tid + 256) >> 3;    // output 1: n
    const int J0 = blk * 8;
    float creg0 = 0.0f, creg1 = 0.0f;     // cell state in registers

    for (int t = 0; t < TT; t++) {
        const int par = t & 1;
        const __nv_bfloat16* __restrict__ hh = g_hh[par];
        const __nv_bfloat16* __restrict__ hl = g_hl[par];

        float d[2][4];
#pragma unroll
        for (int mt = 0; mt < 2; mt++)
#pragma unroll
            for (int r = 0; r < 4; r++) d[mt][r] = 0.0f;

        // Prologue: load slab 0 (hi, k0=0) into buf 0
        {
            __nv_bfloat16* dst = hsm;
#pragma unroll
            for (int i = 0; i < 2; i++) {
                int idx = tid + i * 256;
                int n = idx >> 3, ch = idx & 7;
                cp16(&dst[n * HS_STR + ch * 8], &hh[n * HH + ch * 8]);
            }
            asm volatile("cp.async.commit_group;");
        }

        // 32 slabs: 0-15 over h_hi (mma vs W_hi and W_lo), 16-31 over h_lo (vs W_hi)
        for (int s = 0; s < 32; s++) {
            if (s + 1 < 32) {
                const __nv_bfloat16* src = (s + 1 < 16) ? hh : hl;
                const int k0n = ((s + 1) & 15) * 64;
                __nv_bfloat16* dst = hsm + ((s + 1) & 1) * 64 * HS_STR;
#pragma unroll
                for (int i = 0; i < 2; i++) {
                    int idx = tid + i * 256;
                    int n = idx >> 3, ch = idx & 7;
                    cp16(&dst[n * HS_STR + ch * 8], &src[n * HH + k0n + ch * 8]);
                }
                asm volatile("cp.async.commit_group;");
                asm volatile("cp.async.wait_group 1;");
            } else {
                asm volatile("cp.async.wait_group 0;");
            }
            __syncthreads();

            const __nv_bfloat16* hbuf = hsm + (s & 1) * 64 * HS_STR;
            const bool hiph = (s < 16);
            const int kw = (s & 15) * 64;   // ws row base within region

#pragma unroll
            for (int ks = 0; ks < 4; ks++) {
                const int kk0 = ks * 16;
                // A fragments (shared by both B products)
                unsigned a[2][4];
#pragma unroll
                for (int mt = 0; mt < 2; mt++) {
                    int row = warp_m * 32 + mt * 16 + a_row_off;
                    unsigned addr = s2u(&hbuf[row * HS_STR + kk0 + a_k_off]);
                    asm volatile(
                        "ldmatrix.sync.aligned.m8n8.x4.shared.b16 {%0,%1,%2,%3}, [%4];"
                        : "=r"(a[mt][0]), "=r"(a[mt][1]), "=r"(a[mt][2]), "=r"(a[mt][3])
                        : "r"(addr));
                }
                // B hi fragment
                {
                    unsigned b0, b1;
                    unsigned addr = s2u(&ws[(kw + kk0 + b_krow) * WS_STR + warp_c * 8]);
                    asm volatile(
                        "ldmatrix.sync.aligned.m8n8.x2.trans.shared.b16 {%0,%1}, [%2];"
                        : "=r"(b0), "=r"(b1) : "r"(addr));
#pragma unroll
                    for (int mt = 0; mt < 2; mt++)
                        asm volatile(
                            "mma.sync.aligned.m16n8k16.row.col.f32.bf16.bf16.f32 "
                            "{%0,%1,%2,%3}, {%4,%5,%6,%7}, {%8,%9}, {%0,%1,%2,%3};"
                            : "+f"(d[mt][0]), "+f"(d[mt][1]), "+f"(d[mt][2]), "+f"(d[mt][3])
                            : "r"(a[mt][0]), "r"(a[mt][1]), "r"(a[mt][2]), "r"(a[mt][3]),
                              "r"(b0), "r"(b1));
                }
                // B lo fragment (only for h_hi slabs)
                if (hiph) {
                    unsigned b0, b1;
                    unsigned addr = s2u(&ws[(1024 + kw + kk0 + b_krow) * WS_STR + warp_c * 8]);
                    asm volatile(
                        "ldmatrix.sync.aligned.m8n8.x2.trans.shared.b16 {%0,%1}, [%2];"
                        : "=r"(b0), "=r"(b1) : "r"(addr));
#pragma unroll
                    for (int mt = 0; mt < 2; mt++)
                        asm volatile(
                            "mma.sync.aligned.m16n8k16.row.col.f32.bf16.bf16.f32 "
                            "{%0,%1,%2,%3}, {%4,%5,%6,%7}, {%8,%9}, {%0,%1,%2,%3};"
                            : "+f"(d[mt][0]), "+f"(d[mt][1]), "+f"(d[mt][2]), "+f"(d[mt][3])
                            : "r"(a[mt][0]), "r"(a[mt][1]), "r"(a[mt][2]), "r"(a[mt][3]),
                              "r"(b0), "r"(b1));
                }
            }
            __syncthreads();
        }

        // Scatter accumulators to zbuf[n][c]
        {
            const int r4 = lane >> 2;
            const int c2 = (lane & 3) * 2;
            const int c = warp_c * 8 + c2;
#pragma unroll
            for (int mt = 0; mt < 2; mt++) {
                int n = warp_m * 32 + mt * 16 + r4;
                zbuf[n * 33 + c] = d[mt][0];
                zbuf[n * 33 + c + 1] = d[mt][1];
                zbuf[(n + 8) * 33 + c] = d[mt][2];
                zbuf[(n + 8) * 33 + c + 1] = d[mt][3];
            }
        }
        __syncthreads();

        // Gate epilogue: 2 fixed (n, j) outputs per thread; c kept in registers
        const float* xzt = g_xz + (size_t)(t * NB) * FH;
        __nv_bfloat16* __restrict__ hhn = g_hh[par ^ 1];
        __nv_bfloat16* __restrict__ hln = g_hl[par ^ 1];
#pragma unroll
        for (int s = 0; s < 2; s++) {
            const int n = s ? e_n1 : e_n0;
            const int col = J0 + e_j;
            const float* xr = xzt + (size_t)n * FH + col;
            float zi = zbuf[n * 33 + e_j +  0] + xr[0];
            float zf = zbuf[n * 33 + e_j +  8] + xr[1024];
            float zo = zbuf[n * 33 + e_j + 16] + xr[2048];
            float zg = zbuf[n * 33 + e_j + 24] + xr[3072];

            float iv = 1.0f / (1.0f + expf(-zi));
            float fv = 1.0f / (1.0f + expf(-zf));
            float ov = 1.0f / (1.0f + expf(-zo));
            float gv = tanhf(zg);

            float cprev = s ? creg1 : creg0;
            float cn = fv * cprev + iv * gv;
            if (s) creg1 = cn; else creg0 = cn;
            float hn = ov * tanhf(cn);

            int hidx = n * HH + col;
            __nv_bfloat16 hi = __float2bfloat16(hn);
            hhn[hidx] = hi;
            hln[hidx] = __float2bfloat16(hn - __bfloat162float(hi));
            out[((size_t)n * TT + t) * HH + col] = hn;
        }

        // Grid-wide barrier (sense via monotonically increasing phase)
        if (t + 1 < TT) {
            __syncthreads();
            if (tid == 0) {
                const unsigned target = (unsigned)(t + 1);
                __threadfence();
                unsigned old = atomicAdd(&g_bar_count, 1);
                if (old == gridDim.x - 1) {
                    g_bar_count = 0;
                    st_release(&g_bar_phase, target);
                } else {
                    while (ld_acquire(&g_bar_phase) < target) {}
                }
            }
            __syncthreads();
        }
    }
}

// ---------------------------------------------------------------------------
// Launcher (graph-capturable: kernel launches only)
// ---------------------------------------------------------------------------
extern "C" void kernel_launch(void* const* d_in, const int* in_sizes, int n_in,
                              void* d_out, int out_size) {
    const float* x  = (const float*)d_in[0];
    const float* h0 = (const float*)d_in[1];
    const float* Wx = (const float*)d_in[2];
    const float* Wh = (const float*)d_in[3];
    const float* b  = (const float*)d_in[4];
    float* out = (float*)d_out;

    init_kernel<<<(NB * HH + 255) / 256, 256>>>(h0);
    split_wh_kernel<<<(DD * FH + 255) / 256, 256>>>(Wh);

    dim3 g1(FH / BN, (NB * TT) / BM);   // (32, 256)
    gemm1_kernel<<<g1, 256>>>(x, Wx, b);

    static int smem_set = 0;
    if (!smem_set) {
        cudaFuncSetAttribute(lstm_persistent,
                             cudaFuncAttributeMaxDynamicSharedMemorySize, SMEM_TOTAL);
        smem_set = 1;
    }
    lstm_persistent<<<128, 256, SMEM_TOTAL>>>(out);
}

// round 6
// speedup vs baseline: 2.5384x; 1.4369x over previous
#include <cuda_runtime.h>
#include <cuda_bf16.h>
#include <math.h>

#define NB 64
#define TT 512
#define DD 1024
#define HH 1024
#define FH 4096   // 4*H
#define MM 32768  // NB*TT

typedef unsigned long long ull;

// Scratch (device globals — no runtime allocation allowed)
__device__ float g_xz[(size_t)TT * NB * FH];              // (t, n, 4H) : 512 MB
__device__ __nv_bfloat16 g_wsplit[(size_t)2048 * FH];     // Wh hi|lo, cols permuted
__device__ __nv_bfloat16 g_wxstack[(size_t)3072 * FH];    // [Wx_hi; Wx_lo; Wx_hi]
__device__ __nv_bfloat16 g_xh[(size_t)MM * DD];           // x hi
__device__ __nv_bfloat16 g_xl[(size_t)MM * DD];           // x lo
__device__ __nv_bfloat16 g_hh[2][NB * HH];                // h hi, double-buffered
__device__ __nv_bfloat16 g_hl[2][NB * HH];                // h lo
__device__ unsigned g_bar_count;
__device__ unsigned g_bar_phase;

// ---- helpers ----------------------------------------------------------------
__device__ __forceinline__ unsigned s2u(const void* p) {
    return (unsigned)__cvta_generic_to_shared(p);
}
__device__ __forceinline__ void cp16(void* s, const void* g) {
    asm volatile("cp.async.cg.shared.global [%0], [%1], 16;" :: "r"(s2u(s)), "l"(g));
}
__device__ __forceinline__ unsigned ld_acquire(unsigned* p) {
    unsigned v;
    asm volatile("ld.acquire.gpu.u32 %0, [%1];" : "=r"(v) : "l"(p) : "memory");
    return v;
}
__device__ __forceinline__ void st_release(unsigned* p, unsigned v) {
    asm volatile("st.release.gpu.u32 [%0], %1;" :: "l"(p), "r"(v) : "memory");
}
#define LDSM_X4(r0, r1, r2, r3, addr) \
    asm volatile("ldmatrix.sync.aligned.m8n8.x4.shared.b16 {%0,%1,%2,%3}, [%4];" \
                 : "=r"(r0), "=r"(r1), "=r"(r2), "=r"(r3) : "r"(addr))
#define LDSM_X2T(r0, r1, addr) \
    asm volatile("ldmatrix.sync.aligned.m8n8.x2.trans.shared.b16 {%0,%1}, [%2];" \
                 : "=r"(r0), "=r"(r1) : "r"(addr))
#define LDSM_X4T(r0, r1, r2, r3, addr) \
    asm volatile("ldmatrix.sync.aligned.m8n8.x4.trans.shared.b16 {%0,%1,%2,%3}, [%4];" \
                 : "=r"(r0), "=r"(r1), "=r"(r2), "=r"(r3) : "r"(addr))
#define MMA16816(d0, d1, d2, d3, a0, a1, a2, a3, b0, b1) \
    asm volatile("mma.sync.aligned.m16n8k16.row.col.f32.bf16.bf16.f32 " \
                 "{%0,%1,%2,%3}, {%4,%5,%6,%7}, {%8,%9}, {%0,%1,%2,%3};" \
                 : "+f"(d0), "+f"(d1), "+f"(d2), "+f"(d3) \
                 : "r"(a0), "r"(a1), "r"(a2), "r"(a3), "r"(b0), "r"(b1))

// ---------------------------------------------------------------------------
// Init / precompute kernels
// ---------------------------------------------------------------------------
__global__ void init_kernel(const float* __restrict__ h0) {
    int i = blockIdx.x * blockDim.x + threadIdx.x;
    if (i == 0) { g_bar_count = 0; g_bar_phase = 0; }
    if (i < NB * HH) {
        float v = h0[i];
        __nv_bfloat16 hi = __float2bfloat16(v);
        g_hh[0][i] = hi;
        g_hl[0][i] = __float2bfloat16(v - __bfloat162float(hi));
    }
}

// Wh split + block-column permute: col_new = blk*32 + g*8 + j
__global__ void split_wh_kernel(const float* __restrict__ Wh) {
    int i = blockIdx.x * blockDim.x + threadIdx.x;
    if (i >= DD * FH) return;
    int k = i >> 12;
    int co = i & 4095;
    float w = Wh[i];
    __nv_bfloat16 hi = __float2bfloat16(w);
    __nv_bfloat16 lo = __float2bfloat16(w - __bfloat162float(hi));
    int g = co >> 10;
    int within = co & 1023;
    int blk = within >> 3;
    int j = within & 7;
    size_t col = (size_t)blk * 32 + g * 8 + j;
    g_wsplit[(size_t)k * FH + col] = hi;
    g_wsplit[(size_t)(k + 1024) * FH + col] = lo;
}

// Wx split stacked: rows [0,1024): hi, [1024,2048): lo, [2048,3072): hi
__global__ void split_wx_kernel(const float* __restrict__ Wx) {
    int i = blockIdx.x * blockDim.x + threadIdx.x;
    if (i >= DD * FH) return;
    int k = i >> 12;
    int co = i & 4095;
    float w = Wx[i];
    __nv_bfloat16 hi = __float2bfloat16(w);
    __nv_bfloat16 lo = __float2bfloat16(w - __bfloat162float(hi));
    g_wxstack[(size_t)k * FH + co] = hi;
    g_wxstack[(size_t)(k + 1024) * FH + co] = lo;
    g_wxstack[(size_t)(k + 2048) * FH + co] = hi;
}

// x split
__global__ void split_x_kernel(const float* __restrict__ X) {
    size_t i = (size_t)blockIdx.x * blockDim.x + threadIdx.x;
    if (i >= (size_t)MM * DD) return;
    float v = X[i];
    __nv_bfloat16 hi = __float2bfloat16(v);
    g_xh[i] = hi;
    g_xl[i] = __float2bfloat16(v - __bfloat162float(hi));
}

// ---------------------------------------------------------------------------
// GEMM1 (split-bf16 MMA): xz = x @ Wx + b, K-stacked 3072.
// 128x128x32 tiles, 256 threads (8 warps: 4m x 2n), 3-stage cp.async.
// Epilogue permutes row m=(n*512+t) -> xz row (t*64+n), adds bias.
// ---------------------------------------------------------------------------
#define G1_ASTR 40    // bf16; 80 B rows
#define G1_BSTR 136   // bf16; 272 B rows
#define G1_ABYTES (128 * G1_ASTR * 2)    // 10240
#define G1_BBYTES (32 * G1_BSTR * 2)     // 8704
#define G1_STAGE  (G1_ABYTES + G1_BBYTES)
#define G1_SMEM   (3 * G1_STAGE)         // 56832
#define G1_NSLAB  96

__global__ __launch_bounds__(256) void gemm1_mma(const float* __restrict__ b) {
    extern __shared__ __align__(16) char sm1[];

    const int tid = threadIdx.x;
    const int lane = tid & 31;
    const int wid = tid >> 5;
    const int warp_m = wid >> 1;   // 0..3
    const int warp_n = wid & 1;    // 0..1
    const int m0 = blockIdx.y * 128;
    const int n0 = blockIdx.x * 128;

    // ldmatrix lane addressing
    const int lr = lane & 7;
    const int lg = lane >> 3;
    const int a_row_off = ((lg & 1) << 3) + lr;
    const int a_k_off = (lg >> 1) << 3;
    const int bt_row = lr + ((lg & 1) << 3);   // k row within 16
    const int bt_c8 = (lane >> 4) << 3;        // 0 or 8

    float d[2][8][4];
#pragma unroll
    for (int mt = 0; mt < 2; mt++)
#pragma unroll
        for (int nt = 0; nt < 8; nt++)
#pragma unroll
            for (int r = 0; r < 4; r++) d[mt][nt][r] = 0.0f;

    auto prefetch = [&](int sp) {
        char* stg = sm1 + (sp % 3) * G1_STAGE;
        __nv_bfloat16* As = (__nv_bfloat16*)stg;
        __nv_bfloat16* Bs = (__nv_bfloat16*)(stg + G1_ABYTES);
        const __nv_bfloat16* asrc = (sp < 64) ? g_xh : g_xl;
        const int kin = (sp * 32) & 1023;
#pragma unroll
        for (int i = 0; i < 2; i++) {
            int idx = tid + i * 256;        // A: 512 chunks
            int row = idx >> 2, ch = idx & 3;
            cp16(&As[row * G1_ASTR + ch * 8],
                 &asrc[(size_t)(m0 + row) * DD + kin + ch * 8]);
        }
#pragma unroll
        for (int i = 0; i < 2; i++) {
            int idx = tid + i * 256;        // B: 512 chunks
            int row = idx >> 4, ch = idx & 15;
            cp16(&Bs[row * G1_BSTR + ch * 8],
                 &g_wxstack[(size_t)(sp * 32 + row) * FH + n0 + ch * 8]);
        }
        asm volatile("cp.async.commit_group;");
    };

    prefetch(0);
    prefetch(1);

    for (int s = 0; s < G1_NSLAB; s++) {
        asm volatile("cp.async.wait_group 1;");
        __syncthreads();
        if (s + 2 < G1_NSLAB) prefetch(s + 2);
        else asm volatile("cp.async.commit_group;");

        char* stg = sm1 + (s % 3) * G1_STAGE;
        const __nv_bfloat16* As = (const __nv_bfloat16*)stg;
        const __nv_bfloat16* Bs = (const __nv_bfloat16*)(stg + G1_ABYTES);

#pragma unroll
        for (int ks = 0; ks < 2; ks++) {
            const int kk0 = ks * 16;
            unsigned a[2][4];
#pragma unroll
            for (int mt = 0; mt < 2; mt++) {
                unsigned addr = s2u(&As[(warp_m * 32 + mt * 16 + a_row_off) * G1_ASTR
                                        + kk0 + a_k_off]);
                LDSM_X4(a[mt][0], a[mt][1], a[mt][2], a[mt][3], addr);
            }
            unsigned bf[4][4];
#pragma unroll
            for (int np = 0; np < 4; np++) {
                unsigned addr = s2u(&Bs[(kk0 + bt_row) * G1_BSTR
                                        + warp_n * 64 + np * 16 + bt_c8]);
                LDSM_X4T(bf[np][0], bf[np][1], bf[np][2], bf[np][3], addr);
            }
#pragma unroll
            for (int mt = 0; mt < 2; mt++)
#pragma unroll
                for (int nt = 0; nt < 8; nt++) {
                    unsigned b0 = bf[nt >> 1][(nt & 1) * 2 + 0];
                    unsigned b1 = bf[nt >> 1][(nt & 1) * 2 + 1];
                    MMA16816(d[mt][nt][0], d[mt][nt][1], d[mt][nt][2], d[mt][nt][3],
                             a[mt][0], a[mt][1], a[mt][2], a[mt][3], b0, b1);
                }
        }
    }

    // Epilogue: bias + permuted store
    const int r4 = lane >> 2;
    const int c2 = (lane & 3) * 2;
#pragma unroll
    for (int mt = 0; mt < 2; mt++) {
        int mbase = m0 + warp_m * 32 + mt * 16;
#pragma unroll
        for (int nt = 0; nt < 8; nt++) {
            int col = n0 + warp_n * 64 + nt * 8 + c2;
            float b0 = b[col], b1 = b[col + 1];
            int m = mbase + r4;
            int nb = m >> 9, tl = m & 511;
            float2 v0 = {d[mt][nt][0] + b0, d[mt][nt][1] + b1};
            *(float2*)&g_xz[(size_t)(tl * NB + nb) * FH + col] = v0;
            m += 8; nb = m >> 9; tl = m & 511;
            float2 v1 = {d[mt][nt][2] + b0, d[mt][nt][3] + b1};
            *(float2*)&g_xz[(size_t)(tl * NB + nb) * FH + col] = v1;
        }
    }
}

// ---------------------------------------------------------------------------
// Persistent recurrence kernel. 128 blocks x 512 threads (16 warps:
// 2(k-split) x 2(m) x 4(c)). W slice resident in SMEM; h slabs (128-wide)
// streamed via 3-stage cp.async, 1 syncthreads per slab.
// Split-bf16: z = h_hi*W_hi + h_hi*W_lo + h_lo*W_hi.
// ---------------------------------------------------------------------------
#define WS_STR 40    // bf16; 80 B rows
#define HS_STR 136   // bf16; 272 B rows
#define KSLAB 128
#define HS_STAGE_B (64 * HS_STR * 2)                 // 17408
#define SMEM_WS_B (2048 * WS_STR * 2)                // 163840
#define P_SMEM (SMEM_WS_B + 3 * HS_STAGE_B)          // 216064

__global__ __launch_bounds__(512, 1) void lstm_persistent(float* __restrict__ out) {
    extern __shared__ __align__(16) char smp[];
    __nv_bfloat16* ws = (__nv_bfloat16*)smp;                  // [2048][WS_STR]
    __nv_bfloat16* hsm = (__nv_bfloat16*)(smp + SMEM_WS_B);   // 3 stages
    float* zbuf = (float*)(smp + SMEM_WS_B);                  // aliased: [2][64][33]

    const int tid = threadIdx.x;
    const int lane = tid & 31;
    const int wid = tid >> 5;
    const int warp_k = wid >> 3;        // 0..1
    const int warp_m = (wid >> 2) & 1;  // 0..1
    const int warp_c = wid & 3;         // 0..3
    const int blk = blockIdx.x;

    // --- Load this block's W slice into SMEM (once) ---
    {
        const __nv_bfloat16* wsrc = g_wsplit + (size_t)blk * 32;
#pragma unroll
        for (int i = 0; i < 16; i++) {
            int c = tid + i * 512;          // 0..8191 16B-chunks
            int row = c >> 2, q = c & 3;
            *(uint4*)&ws[row * WS_STR + q * 8] =
                *(const uint4*)&wsrc[(size_t)row * FH + q * 8];
        }
    }
    __syncthreads();

    // ldmatrix lane addressing
    const int lr = lane & 7;
    const int lg = lane >> 3;
    const int a_row_off = ((lg & 1) << 3) + lr;
    const int a_k_off = (lg >> 1) << 3;
    const int b_krow = lane & 15;

    // epilogue mapping: 1 output per thread
    const int e_n = tid >> 3;
    const int e_j = tid & 7;
    const int J0 = blk * 8;
    float creg = 0.0f;

    for (int t = 0; t < TT; t++) {
        const int par = t & 1;
        const __nv_bfloat16* __restrict__ hh = g_hh[par];
        const __nv_bfloat16* __restrict__ hl = g_hl[par];

        float d[2][4];
#pragma unroll
        for (int mt = 0; mt < 2; mt++)
#pragma unroll
            for (int r = 0; r < 4; r++) d[mt][r] = 0.0f;

        // Slabs: 0-7 h_hi (2 B-products), 8-15 h_lo (W_hi only)
        auto prefetch = [&](int sp) {
            const __nv_bfloat16* src = (sp < 8) ? hh : hl;
            const int hk = (sp & 7) * KSLAB;
            __nv_bfloat16* dst = hsm + (sp % 3) * 64 * HS_STR;
#pragma unroll
            for (int i = 0; i < 2; i++) {
                int idx = tid + i * 512;    // 1024 chunks
                int n = idx >> 4, ch = idx & 15;
                cp16(&dst[n * HS_STR + ch * 8], &src[n * HH + hk + ch * 8]);
            }
            asm volatile("cp.async.commit_group;");
        };

        prefetch(0);
        prefetch(1);

        for (int s = 0; s < 16; s++) {
            asm volatile("cp.async.wait_group 1;");
            __syncthreads();
            if (s + 2 < 16) prefetch(s + 2);
            else asm volatile("cp.async.commit_group;");

            const __nv_bfloat16* hbuf = hsm + (s % 3) * 64 * HS_STR;
            const bool hiph = (s < 8);
            const int kw = (s & 7) * KSLAB;

#pragma unroll
            for (int ks = 0; ks < 4; ks++) {
                const int kk0 = warp_k * 64 + ks * 16;
                unsigned a[2][4];
#pragma unroll
                for (int mt = 0; mt < 2; mt++) {
                    unsigned addr = s2u(&hbuf[(warp_m * 32 + mt * 16 + a_row_off) * HS_STR
                                              + kk0 + a_k_off]);
                    LDSM_X4(a[mt][0], a[mt][1], a[mt][2], a[mt][3], addr);
                }
                {   // W_hi product
                    unsigned b0, b1;
                    unsigned addr = s2u(&ws[(kw + kk0 + b_krow) * WS_STR + warp_c * 8]);
                    LDSM_X2T(b0, b1, addr);
#pragma unroll
                    for (int mt = 0; mt < 2; mt++)
                        MMA16816(d[mt][0], d[mt][1], d[mt][2], d[mt][3],
                                 a[mt][0], a[mt][1], a[mt][2], a[mt][3], b0, b1);
                }
                if (hiph) {   // W_lo product
                    unsigned b0, b1;
                    unsigned addr = s2u(&ws[(1024 + kw + kk0 + b_krow) * WS_STR + warp_c * 8]);
                    LDSM_X2T(b0, b1, addr);
#pragma unroll
                    for (int mt = 0; mt < 2; mt++)
                        MMA16816(d[mt][0], d[mt][1], d[mt][2], d[mt][3],
                                 a[mt][0], a[mt][1], a[mt][2], a[mt][3], b0, b1);
                }
            }
        }
        asm volatile("cp.async.wait_group 0;");
        __syncthreads();   // all computing done; zbuf (aliased stage 0) now safe

        // Scatter partials: zbuf[warp_k][n][c]
        {
            const int r4 = lane >> 2;
            const int c2 = (lane & 3) * 2;
            const int c = warp_c * 8 + c2;
#pragma unroll
            for (int mt = 0; mt < 2; mt++) {
                int n = warp_m * 32 + mt * 16 + r4;
                zbuf[(warp_k * 64 + n) * 33 + c] = d[mt][0];
                zbuf[(warp_k * 64 + n) * 33 + c + 1] = d[mt][1];
                zbuf[(warp_k * 64 + n + 8) * 33 + c] = d[mt][2];
                zbuf[(warp_k * 64 + n + 8) * 33 + c + 1] = d[mt][3];
            }
        }
        __syncthreads();

        // Gate epilogue: 1 fixed (n, j) output per thread; c in register
        {
            const int n = e_n, col = J0 + e_j;
            const float* xr = g_xz + (size_t)(t * NB + n) * FH + col;
            float zi = zbuf[n * 33 + e_j +  0] + zbuf[(64 + n) * 33 + e_j +  0] + xr[0];
            float zf = zbuf[n * 33 + e_j +  8] + zbuf[(64 + n) * 33 + e_j +  8] + xr[1024];
            float zo = zbuf[n * 33 + e_j + 16] + zbuf[(64 + n) * 33 + e_j + 16] + xr[2048];
            float zg = zbuf[n * 33 + e_j + 24] + zbuf[(64 + n) * 33 + e_j + 24] + xr[3072];

            float iv = 1.0f / (1.0f + expf(-zi));
            float fv = 1.0f / (1.0f + expf(-zf));
            float ov = 1.0f / (1.0f + expf(-zo));
            float gv = tanhf(zg);

            float cn = fv * creg + iv * gv;
            creg = cn;
            float hn = ov * tanhf(cn);

            int hidx = n * HH + col;
            __nv_bfloat16 hi = __float2bfloat16(hn);
            g_hh[par ^ 1][hidx] = hi;
            g_hl[par ^ 1][hidx] = __float2bfloat16(hn - __bfloat162float(hi));
            out[((size_t)n * TT + t) * HH + col] = hn;
        }

        // Grid-wide barrier
        if (t + 1 < TT) {
            __syncthreads();
            if (tid == 0) {
                const unsigned target = (unsigned)(t + 1);
                __threadfence();
                unsigned old = atomicAdd(&g_bar_count, 1);
                if (old == gridDim.x - 1) {
                    g_bar_count = 0;
                    st_release(&g_bar_phase, target);
                } else {
                    while (ld_acquire(&g_bar_phase) < target) {}
                }
            }
            __syncthreads();
        }
    }
}

// ---------------------------------------------------------------------------
// Launcher (graph-capturable: kernel launches only)
// ---------------------------------------------------------------------------
extern "C" void kernel_launch(void* const* d_in, const int* in_sizes, int n_in,
                              void* d_out, int out_size) {
    const float* x  = (const float*)d_in[0];
    const float* h0 = (const float*)d_in[1];
    const float* Wx = (const float*)d_in[2];
    const float* Wh = (const float*)d_in[3];
    const float* b  = (const float*)d_in[4];
    float* out = (float*)d_out;

    static int attr_set = 0;
    if (!attr_set) {
        cudaFuncSetAttribute(lstm_persistent,
                             cudaFuncAttributeMaxDynamicSharedMemorySize, P_SMEM);
        cudaFuncSetAttribute(gemm1_mma,
                             cudaFuncAttributeMaxDynamicSharedMemorySize, G1_SMEM);
        attr_set = 1;
    }

    init_kernel<<<(NB * HH + 255) / 256, 256>>>(h0);
    split_wh_kernel<<<(DD * FH + 255) / 256, 256>>>(Wh);
    split_wx_kernel<<<(DD * FH + 255) / 256, 256>>>(Wx);
    split_x_kernel<<<((size_t)MM * DD + 511) / 512, 512>>>(x);

    dim3 g1(FH / 128, MM / 128);   // (32, 256)
    gemm1_mma<<<g1, 256, G1_SMEM>>>(b);

    lstm_persistent<<<128, 512, P_SMEM>>>(out);
}

// round 7
// speedup vs baseline: 2.6817x; 1.0565x over previous
#include <cuda_runtime.h>
#include <cuda_bf16.h>
#include <math.h>

#define NB 64
#define TT 512
#define DD 1024
#define HH 1024
#define FH 4096   // 4*H
#define MM 32768  // NB*TT

typedef unsigned long long ull;

// Scratch (device globals — no runtime allocation allowed)
__device__ float g_xz[(size_t)TT * NB * FH];              // (t, n, 4H) : 512 MB
__device__ __nv_bfloat16 g_wsplit[(size_t)2048 * FH];     // Wh hi|lo, cols permuted
__device__ __nv_bfloat16 g_wxstack[(size_t)3072 * FH];    // [Wx_hi; Wx_lo; Wx_hi]
__device__ __nv_bfloat16 g_xh[(size_t)MM * DD];           // x hi
__device__ __nv_bfloat16 g_xl[(size_t)MM * DD];           // x lo
__device__ __nv_bfloat16 g_hh[2][NB * HH];                // h hi, double-buffered
__device__ __nv_bfloat16 g_hl[2][NB * HH];                // h lo
__device__ unsigned g_bar_count;
__device__ unsigned g_bar_phase;

// ---- helpers ----------------------------------------------------------------
__device__ __forceinline__ unsigned s2u(const void* p) {
    return (unsigned)__cvta_generic_to_shared(p);
}
__device__ __forceinline__ void cp16(void* s, const void* g) {
    asm volatile("cp.async.cg.shared.global [%0], [%1], 16;" :: "r"(s2u(s)), "l"(g));
}
__device__ __forceinline__ unsigned ld_acquire(unsigned* p) {
    unsigned v;
    asm volatile("ld.acquire.gpu.u32 %0, [%1];" : "=r"(v) : "l"(p) : "memory");
    return v;
}
__device__ __forceinline__ void st_release(unsigned* p, unsigned v) {
    asm volatile("st.release.gpu.u32 [%0], %1;" :: "l"(p), "r"(v) : "memory");
}
#define LDSM_X4(r0, r1, r2, r3, addr) \
    asm volatile("ldmatrix.sync.aligned.m8n8.x4.shared.b16 {%0,%1,%2,%3}, [%4];" \
                 : "=r"(r0), "=r"(r1), "=r"(r2), "=r"(r3) : "r"(addr))
#define LDSM_X2T(r0, r1, addr) \
    asm volatile("ldmatrix.sync.aligned.m8n8.x2.trans.shared.b16 {%0,%1}, [%2];" \
                 : "=r"(r0), "=r"(r1) : "r"(addr))
#define LDSM_X4T(r0, r1, r2, r3, addr) \
    asm volatile("ldmatrix.sync.aligned.m8n8.x4.trans.shared.b16 {%0,%1,%2,%3}, [%4];" \
                 : "=r"(r0), "=r"(r1), "=r"(r2), "=r"(r3) : "r"(addr))
#define MMA16816(d0, d1, d2, d3, a0, a1, a2, a3, b0, b1) \
    asm volatile("mma.sync.aligned.m16n8k16.row.col.f32.bf16.bf16.f32 " \
                 "{%0,%1,%2,%3}, {%4,%5,%6,%7}, {%8,%9}, {%0,%1,%2,%3};" \
                 : "+f"(d0), "+f"(d1), "+f"(d2), "+f"(d3) \
                 : "r"(a0), "r"(a1), "r"(a2), "r"(a3), "r"(b0), "r"(b1))

// ---------------------------------------------------------------------------
// Init / precompute kernels
// ---------------------------------------------------------------------------
__global__ void init_kernel(const float* __restrict__ h0) {
    int i = blockIdx.x * blockDim.x + threadIdx.x;
    if (i == 0) { g_bar_count = 0; g_bar_phase = 0; }
    if (i < NB * HH) {
        float v = h0[i];
        __nv_bfloat16 hi = __float2bfloat16(v);
        g_hh[0][i] = hi;
        g_hl[0][i] = __float2bfloat16(v - __bfloat162float(hi));
    }
}

// Wh split + block-column permute: col_new = blk*32 + g*8 + j
__global__ void split_wh_kernel(const float* __restrict__ Wh) {
    int i = blockIdx.x * blockDim.x + threadIdx.x;
    if (i >= DD * FH) return;
    int k = i >> 12;
    int co = i & 4095;
    float w = Wh[i];
    __nv_bfloat16 hi = __float2bfloat16(w);
    __nv_bfloat16 lo = __float2bfloat16(w - __bfloat162float(hi));
    int g = co >> 10;
    int within = co & 1023;
    int blk = within >> 3;
    int j = within & 7;
    size_t col = (size_t)blk * 32 + g * 8 + j;
    g_wsplit[(size_t)k * FH + col] = hi;
    g_wsplit[(size_t)(k + 1024) * FH + col] = lo;
}

// Wx split stacked: rows [0,1024): hi, [1024,2048): lo, [2048,3072): hi
__global__ void split_wx_kernel(const float* __restrict__ Wx) {
    int i = blockIdx.x * blockDim.x + threadIdx.x;
    if (i >= DD * FH) return;
    int k = i >> 12;
    int co = i & 4095;
    float w = Wx[i];
    __nv_bfloat16 hi = __float2bfloat16(w);
    __nv_bfloat16 lo = __float2bfloat16(w - __bfloat162float(hi));
    g_wxstack[(size_t)k * FH + co] = hi;
    g_wxstack[(size_t)(k + 1024) * FH + co] = lo;
    g_wxstack[(size_t)(k + 2048) * FH + co] = hi;
}

// x split
__global__ void split_x_kernel(const float* __restrict__ X) {
    size_t i = (size_t)blockIdx.x * blockDim.x + threadIdx.x;
    if (i >= (size_t)MM * DD) return;
    float v = X[i];
    __nv_bfloat16 hi = __float2bfloat16(v);
    g_xh[i] = hi;
    g_xl[i] = __float2bfloat16(v - __bfloat162float(hi));
}

// ---------------------------------------------------------------------------
// GEMM1 (split-bf16 MMA): xz = x @ Wx + b, K-stacked 3072.
// 128x128x32 tiles, 256 threads (8 warps: 4m x 2n), 3-stage cp.async.
// ---------------------------------------------------------------------------
#define G1_ASTR 40    // bf16; 80 B rows
#define G1_BSTR 136   // bf16; 272 B rows
#define G1_ABYTES (128 * G1_ASTR * 2)    // 10240
#define G1_BBYTES (32 * G1_BSTR * 2)     // 8704
#define G1_STAGE  (G1_ABYTES + G1_BBYTES)
#define G1_SMEM   (3 * G1_STAGE)         // 56832
#define G1_NSLAB  96

__global__ __launch_bounds__(256) void gemm1_mma(const float* __restrict__ b) {
    extern __shared__ __align__(16) char sm1[];

    const int tid = threadIdx.x;
    const int lane = tid & 31;
    const int wid = tid >> 5;
    const int warp_m = wid >> 1;   // 0..3
    const int warp_n = wid & 1;    // 0..1
    const int m0 = blockIdx.y * 128;
    const int n0 = blockIdx.x * 128;

    const int lr = lane & 7;
    const int lg = lane >> 3;
    const int a_row_off = ((lg & 1) << 3) + lr;
    const int a_k_off = (lg >> 1) << 3;
    const int bt_row = lr + ((lg & 1) << 3);
    const int bt_c8 = (lane >> 4) << 3;

    float d[2][8][4];
#pragma unroll
    for (int mt = 0; mt < 2; mt++)
#pragma unroll
        for (int nt = 0; nt < 8; nt++)
#pragma unroll
            for (int r = 0; r < 4; r++) d[mt][nt][r] = 0.0f;

    auto prefetch = [&](int sp) {
        char* stg = sm1 + (sp % 3) * G1_STAGE;
        __nv_bfloat16* As = (__nv_bfloat16*)stg;
        __nv_bfloat16* Bs = (__nv_bfloat16*)(stg + G1_ABYTES);
        const __nv_bfloat16* asrc = (sp < 64) ? g_xh : g_xl;
        const int kin = (sp * 32) & 1023;
#pragma unroll
        for (int i = 0; i < 2; i++) {
            int idx = tid + i * 256;
            int row = idx >> 2, ch = idx & 3;
            cp16(&As[row * G1_ASTR + ch * 8],
                 &asrc[(size_t)(m0 + row) * DD + kin + ch * 8]);
        }
#pragma unroll
        for (int i = 0; i < 2; i++) {
            int idx = tid + i * 256;
            int row = idx >> 4, ch = idx & 15;
            cp16(&Bs[row * G1_BSTR + ch * 8],
                 &g_wxstack[(size_t)(sp * 32 + row) * FH + n0 + ch * 8]);
        }
        asm volatile("cp.async.commit_group;");
    };

    prefetch(0);
    prefetch(1);

    for (int s = 0; s < G1_NSLAB; s++) {
        asm volatile("cp.async.wait_group 1;");
        __syncthreads();
        if (s + 2 < G1_NSLAB) prefetch(s + 2);
        else asm volatile("cp.async.commit_group;");

        char* stg = sm1 + (s % 3) * G1_STAGE;
        const __nv_bfloat16* As = (const __nv_bfloat16*)stg;
        const __nv_bfloat16* Bs = (const __nv_bfloat16*)(stg + G1_ABYTES);

#pragma unroll
        for (int ks = 0; ks < 2; ks++) {
            const int kk0 = ks * 16;
            unsigned a[2][4];
#pragma unroll
            for (int mt = 0; mt < 2; mt++) {
                unsigned addr = s2u(&As[(warp_m * 32 + mt * 16 + a_row_off) * G1_ASTR
                                        + kk0 + a_k_off]);
                LDSM_X4(a[mt][0], a[mt][1], a[mt][2], a[mt][3], addr);
            }
            unsigned bf[4][4];
#pragma unroll
            for (int np = 0; np < 4; np++) {
                unsigned addr = s2u(&Bs[(kk0 + bt_row) * G1_BSTR
                                        + warp_n * 64 + np * 16 + bt_c8]);
                LDSM_X4T(bf[np][0], bf[np][1], bf[np][2], bf[np][3], addr);
            }
#pragma unroll
            for (int mt = 0; mt < 2; mt++)
#pragma unroll
                for (int nt = 0; nt < 8; nt++) {
                    unsigned b0 = bf[nt >> 1][(nt & 1) * 2 + 0];
                    unsigned b1 = bf[nt >> 1][(nt & 1) * 2 + 1];
                    MMA16816(d[mt][nt][0], d[mt][nt][1], d[mt][nt][2], d[mt][nt][3],
                             a[mt][0], a[mt][1], a[mt][2], a[mt][3], b0, b1);
                }
        }
    }

    // Epilogue: bias + permuted store
    const int r4 = lane >> 2;
    const int c2 = (lane & 3) * 2;
#pragma unroll
    for (int mt = 0; mt < 2; mt++) {
        int mbase = m0 + warp_m * 32 + mt * 16;
#pragma unroll
        for (int nt = 0; nt < 8; nt++) {
            int col = n0 + warp_n * 64 + nt * 8 + c2;
            float b0 = b[col], b1 = b[col + 1];
            int m = mbase + r4;
            int nb = m >> 9, tl = m & 511;
            float2 v0 = {d[mt][nt][0] + b0, d[mt][nt][1] + b1};
            *(float2*)&g_xz[(size_t)(tl * NB + nb) * FH + col] = v0;
            m += 8; nb = m >> 9; tl = m & 511;
            float2 v1 = {d[mt][nt][2] + b0, d[mt][nt][3] + b1};
            *(float2*)&g_xz[(size_t)(tl * NB + nb) * FH + col] = v1;
        }
    }
}

// ---------------------------------------------------------------------------
// Persistent recurrence kernel. 128 blocks x 512 threads (16 warps:
// 2(k-split) x 2(m) x 4(c)). W resident in SMEM; h in 256-wide slabs,
// 2-stage double-buffered cp.async, ONE syncthreads per slab (8/step).
// Split-bf16: z = h_hi*W_hi + h_hi*W_lo + h_lo*W_hi.
// ---------------------------------------------------------------------------
#define WS_STR 40    // bf16; 80 B rows
#define HS_STR 264   // bf16; 528 B rows (odd multiple of 16B)
#define KSLAB 256
#define HS_STAGE_B (64 * HS_STR * 2)                 // 33792
#define SMEM_WS_B (2048 * WS_STR * 2)                // 163840
#define P_SMEM (SMEM_WS_B + 2 * HS_STAGE_B)          // 231424

__global__ __launch_bounds__(512, 1) void lstm_persistent(float* __restrict__ out) {
    extern __shared__ __align__(16) char smp[];
    __nv_bfloat16* ws = (__nv_bfloat16*)smp;                  // [2048][WS_STR]
    __nv_bfloat16* hsm = (__nv_bfloat16*)(smp + SMEM_WS_B);   // 2 stages
    float* zbuf = (float*)(smp + SMEM_WS_B);                  // alias of stage 0

    const int tid = threadIdx.x;
    const int lane = tid & 31;
    const int wid = tid >> 5;
    const int warp_k = wid >> 3;        // 0..1
    const int warp_m = (wid >> 2) & 1;  // 0..1
    const int warp_c = wid & 3;         // 0..3
    const int blk = blockIdx.x;

    // --- Load this block's W slice into SMEM (once) ---
    {
        const __nv_bfloat16* wsrc = g_wsplit + (size_t)blk * 32;
#pragma unroll
        for (int i = 0; i < 16; i++) {
            int c = tid + i * 512;
            int row = c >> 2, q = c & 3;
            *(uint4*)&ws[row * WS_STR + q * 8] =
                *(const uint4*)&wsrc[(size_t)row * FH + q * 8];
        }
    }
    __syncthreads();

    // ldmatrix lane addressing
    const int lr = lane & 7;
    const int lg = lane >> 3;
    const int a_row_off = ((lg & 1) << 3) + lr;
    const int a_k_off = (lg >> 1) << 3;
    const int b_krow = lane & 15;

    // epilogue mapping: 1 output per thread
    const int e_n = tid >> 3;
    const int e_j = tid & 7;
    const int J0 = blk * 8;
    float creg = 0.0f;

    for (int t = 0; t < TT; t++) {
        const int par = t & 1;
        const __nv_bfloat16* __restrict__ hh = g_hh[par];
        const __nv_bfloat16* __restrict__ hl = g_hl[par];

        // Early xz prefetch (DRAM latency hidden behind the slab loop)
        const float* xr = g_xz + (size_t)(t * NB + e_n) * FH + J0 + e_j;
        float x0 = __ldg(xr);
        float x1 = __ldg(xr + 1024);
        float x2 = __ldg(xr + 2048);
        float x3 = __ldg(xr + 3072);

        float d[2][4];
#pragma unroll
        for (int mt = 0; mt < 2; mt++)
#pragma unroll
            for (int r = 0; r < 4; r++) d[mt][r] = 0.0f;

        // Slabs: 0-3 h_hi (W_hi + W_lo), 4-7 h_lo (W_hi only)
        auto prefetch = [&](int sp) {
            const __nv_bfloat16* src = (sp < 4) ? hh : hl;
            const int hk = (sp & 3) * KSLAB;
            __nv_bfloat16* dst = hsm + (sp & 1) * 64 * HS_STR;
#pragma unroll
            for (int i = 0; i < 4; i++) {
                int idx = tid + i * 512;    // 2048 chunks of 16B
                int n = idx >> 5, ch = idx & 31;
                cp16(&dst[n * HS_STR + ch * 8], &src[n * HH + hk + ch * 8]);
            }
            asm volatile("cp.async.commit_group;");
        };

        prefetch(0);

        for (int s = 0; s < 8; s++) {
            asm volatile("cp.async.wait_group 0;");
            __syncthreads();
            if (s + 1 < 8) prefetch(s + 1);

            const __nv_bfloat16* hbuf = hsm + (s & 1) * 64 * HS_STR;
            const bool hiph = (s < 4);
            const int kw = (s & 3) * KSLAB;

#pragma unroll
            for (int ks = 0; ks < 8; ks++) {
                const int kk0 = warp_k * 128 + ks * 16;
                unsigned a[2][4];
#pragma unroll
                for (int mt = 0; mt < 2; mt++) {
                    unsigned addr = s2u(&hbuf[(warp_m * 32 + mt * 16 + a_row_off) * HS_STR
                                              + kk0 + a_k_off]);
                    LDSM_X4(a[mt][0], a[mt][1], a[mt][2], a[mt][3], addr);
                }
                {   // W_hi product
                    unsigned b0, b1;
                    unsigned addr = s2u(&ws[(kw + kk0 + b_krow) * WS_STR + warp_c * 8]);
                    LDSM_X2T(b0, b1, addr);
#pragma unroll
                    for (int mt = 0; mt < 2; mt++)
                        MMA16816(d[mt][0], d[mt][1], d[mt][2], d[mt][3],
                                 a[mt][0], a[mt][1], a[mt][2], a[mt][3], b0, b1);
                }
                if (hiph) {   // W_lo product
                    unsigned b0, b1;
                    unsigned addr = s2u(&ws[(1024 + kw + kk0 + b_krow) * WS_STR + warp_c * 8]);
                    LDSM_X2T(b0, b1, addr);
#pragma unroll
                    for (int mt = 0; mt < 2; mt++)
                        MMA16816(d[mt][0], d[mt][1], d[mt][2], d[mt][3],
                                 a[mt][0], a[mt][1], a[mt][2], a[mt][3], b0, b1);
                }
            }
        }
        __syncthreads();   // all compute done; zbuf (alias of stage 0) now safe

        // Scatter partials: zbuf[warp_k][n][c]
        {
            const int r4 = lane >> 2;
            const int c2 = (lane & 3) * 2;
            const int c = warp_c * 8 + c2;
#pragma unroll
            for (int mt = 0; mt < 2; mt++) {
                int n = warp_m * 32 + mt * 16 + r4;
                zbuf[(warp_k * 64 + n) * 33 + c] = d[mt][0];
                zbuf[(warp_k * 64 + n) * 33 + c + 1] = d[mt][1];
                zbuf[(warp_k * 64 + n + 8) * 33 + c] = d[mt][2];
                zbuf[(warp_k * 64 + n + 8) * 33 + c + 1] = d[mt][3];
            }
        }
        __syncthreads();

        // Gate epilogue: 1 fixed (n, j) output per thread; c in register
        {
            const int n = e_n, col = J0 + e_j;
            float zi = zbuf[n * 33 + e_j +  0] + zbuf[(64 + n) * 33 + e_j +  0] + x0;
            float zf = zbuf[n * 33 + e_j +  8] + zbuf[(64 + n) * 33 + e_j +  8] + x1;
            float zo = zbuf[n * 33 + e_j + 16] + zbuf[(64 + n) * 33 + e_j + 16] + x2;
            float zg = zbuf[n * 33 + e_j + 24] + zbuf[(64 + n) * 33 + e_j + 24] + x3;

            float iv = 1.0f / (1.0f + expf(-zi));
            float fv = 1.0f / (1.0f + expf(-zf));
            float ov = 1.0f / (1.0f + expf(-zo));
            float gv = tanhf(zg);

            float cn = fv * creg + iv * gv;
            creg = cn;
            float hn = ov * tanhf(cn);

            int hidx = n * HH + col;
            __nv_bfloat16 hi = __float2bfloat16(hn);
            g_hh[par ^ 1][hidx] = hi;
            g_hl[par ^ 1][hidx] = __float2bfloat16(hn - __bfloat162float(hi));
            out[((size_t)n * TT + t) * HH + col] = hn;
        }

        // Grid-wide barrier
        if (t + 1 < TT) {
            __syncthreads();
            if (tid == 0) {
                const unsigned target = (unsigned)(t + 1);
                __threadfence();
                unsigned old = atomicAdd(&g_bar_count, 1);
                if (old == gridDim.x - 1) {
                    g_bar_count = 0;
                    st_release(&g_bar_phase, target);
                } else {
                    while (ld_acquire(&g_bar_phase) < target) {}
                }
            }
            __syncthreads();
        }
    }
}

// ---------------------------------------------------------------------------
// Launcher (graph-capturable: kernel launches only)
// ---------------------------------------------------------------------------
extern "C" void kernel_launch(void* const* d_in, const int* in_sizes, int n_in,
                              void* d_out, int out_size) {
    const float* x  = (const float*)d_in[0];
    const float* h0 = (const float*)d_in[1];
    const float* Wx = (const float*)d_in[2];
    const float* Wh = (const float*)d_in[3];
    const float* b  = (const float*)d_in[4];
    float* out = (float*)d_out;

    static int attr_set = 0;
    if (!attr_set) {
        cudaFuncSetAttribute(lstm_persistent,
                             cudaFuncAttributeMaxDynamicSharedMemorySize, P_SMEM);
        cudaFuncSetAttribute(gemm1_mma,
                             cudaFuncAttributeMaxDynamicSharedMemorySize, G1_SMEM);
        attr_set = 1;
    }

    init_kernel<<<(NB * HH + 255) / 256, 256>>>(h0);
    split_wh_kernel<<<(DD * FH + 255) / 256, 256>>>(Wh);
    split_wx_kernel<<<(DD * FH + 255) / 256, 256>>>(Wx);
    split_x_kernel<<<((size_t)MM * DD + 511) / 512, 512>>>(x);

    dim3 g1(FH / 128, MM / 128);   // (32, 256)
    gemm1_mma<<<g1, 256, G1_SMEM>>>(b);

    lstm_persistent<<<128, 512, P_SMEM>>>(out);
}